// round 6
// baseline (speedup 1.0000x reference)
#include <cuda_runtime.h>
#include <math.h>

#define NN    1024      // nodes / seq len
#define NE    16384     // edges
#define BSZ   16
#define LEN0  8500
#define HH    640
#define G4    2560      // 4*H
#define TT    1024
#define SB    128       // scan blocks (must be <= #SMs for co-residency)

// ---------------- device scratch (no allocations allowed) ----------------
__device__ float g_xw[TT * G4];        // 10.5 MB input projection
__device__ float g_seqA[TT * HH];
__device__ float g_seqB[TT * HH];
__device__ float g_hbuf[2 * HH];       // double-buffered h
__device__ int   g_ctr[TT];            // per-step barrier counters
__device__ float g_gh[NN * 320];       // gcn xW
__device__ float g_agg[NN * 320];      // gcn aggregation
__device__ float g_deg[NN];
__device__ float g_dinv[NN];
__device__ float g_cs1[320];           // column sums
__device__ float g_cs2[320];           // column sums of squares

// ---------------- utility ----------------
__global__ void k_zero_f(float* p, int n) {
    int st = gridDim.x * blockDim.x;
    for (int i = blockIdx.x * blockDim.x + threadIdx.x; i < n; i += st) p[i] = 0.f;
}
__global__ void k_zero_ctr() {
    int i = blockIdx.x * blockDim.x + threadIdx.x;
    if (i < TT) g_ctr[i] = 0;
}

// ---------------- SGEMM  C[M,N] = A[M,K] * B[N,K]^T + b0[n] + b1[n] ----------------
// BM=128, BN=64, BK=8, 256 threads, 8x4 microtile. M%128==0, N%64==0, K guarded.
__global__ void __launch_bounds__(256) k_gemm_nt(
    const float* __restrict__ A, const float* __restrict__ B,
    const float* __restrict__ b0, const float* __restrict__ b1,
    float* __restrict__ C, int M, int N, int K)
{
    __shared__ float As[8][128];
    __shared__ float Bs[8][64];
    const int tid = threadIdx.x;
    const int bm = blockIdx.y * 128;
    const int bn = blockIdx.x * 64;
    const int ty = tid >> 4, tx = tid & 15;          // 16x16 thread grid
    const int arow = tid >> 1, ak = (tid & 1) * 4;   // A loader
    const int brow = tid >> 2, bk = (tid & 3) * 2;   // B loader
    const float* Ap = A + (bm + arow) * K;
    const float* Bp = B + (bn + brow) * K;
    float acc[8][4] = {};
    for (int k0 = 0; k0 < K; k0 += 8) {
        #pragma unroll
        for (int i = 0; i < 4; i++) {
            int kk = k0 + ak + i;
            As[ak + i][arow] = (kk < K) ? Ap[kk] : 0.f;
        }
        #pragma unroll
        for (int i = 0; i < 2; i++) {
            int kk = k0 + bk + i;
            Bs[bk + i][brow] = (kk < K) ? Bp[kk] : 0.f;
        }
        __syncthreads();
        #pragma unroll
        for (int kk = 0; kk < 8; kk++) {
            float ra[8], rb[4];
            #pragma unroll
            for (int i = 0; i < 8; i++) ra[i] = As[kk][ty * 8 + i];
            #pragma unroll
            for (int j = 0; j < 4; j++) rb[j] = Bs[kk][tx * 4 + j];
            #pragma unroll
            for (int i = 0; i < 8; i++)
                #pragma unroll
                for (int j = 0; j < 4; j++)
                    acc[i][j] += ra[i] * rb[j];
        }
        __syncthreads();
    }
    #pragma unroll
    for (int i = 0; i < 8; i++) {
        int m = bm + ty * 8 + i;
        #pragma unroll
        for (int j = 0; j < 4; j++) {
            int n = bn + tx * 4 + j;
            C[m * N + n] = acc[i][j] + b0[n] + b1[n];
        }
    }
}

// ---------------- GEMM NN for GCN:  C[1024,N] = A[1024,K] * B[K,N] ----------------
// BM=64, BN=64 (N-guarded), BK=8, 256 threads, 4x4 microtile.
__global__ void __launch_bounds__(256) k_gemm_nn(
    const float* __restrict__ A, const float* __restrict__ B,
    float* __restrict__ C, int N, int K)
{
    __shared__ float As[8][64];
    __shared__ float Bs[8][64];
    const int tid = threadIdx.x;
    const int bm = blockIdx.y * 64;
    const int bn = blockIdx.x * 64;
    const int ty = tid >> 4, tx = tid & 15;
    const int arow = tid >> 2, ak = (tid & 3) * 2;
    const int bkr = tid >> 5, bc = (tid & 31) * 2;
    float acc[4][4] = {};
    for (int k0 = 0; k0 < K; k0 += 8) {
        #pragma unroll
        for (int i = 0; i < 2; i++) {
            int kk = k0 + ak + i;
            As[ak + i][arow] = (kk < K) ? A[(bm + arow) * K + kk] : 0.f;
        }
        #pragma unroll
        for (int i = 0; i < 2; i++) {
            int n = bn + bc + i;
            Bs[bkr][bc + i] = (k0 + bkr < K && n < N) ? B[(k0 + bkr) * N + n] : 0.f;
        }
        __syncthreads();
        #pragma unroll
        for (int kk = 0; kk < 8; kk++) {
            float ra[4], rb[4];
            #pragma unroll
            for (int i = 0; i < 4; i++) ra[i] = As[kk][ty * 4 + i];
            #pragma unroll
            for (int j = 0; j < 4; j++) rb[j] = Bs[kk][tx * 4 + j];
            #pragma unroll
            for (int i = 0; i < 4; i++)
                #pragma unroll
                for (int j = 0; j < 4; j++)
                    acc[i][j] += ra[i] * rb[j];
        }
        __syncthreads();
    }
    #pragma unroll
    for (int i = 0; i < 4; i++) {
        int m = bm + ty * 4 + i;
        #pragma unroll
        for (int j = 0; j < 4; j++) {
            int n = bn + tx * 4 + j;
            if (n < N) C[m * N + n] = acc[i][j];
        }
    }
}

// ---------------- LSTM recurrent scan ----------------
// 128 blocks x 160 threads. Block b owns h elements [5b, 5b+5).
// Warp e (0..4) computes ALL FOUR gate rows of element j = 5b+e, with the
// Whh weights resident in registers (80 per thread) for the whole sequence.
// Cross-block step barrier: per-step counter + spin (all 128 CTAs co-resident).
__global__ void __launch_bounds__(160) k_lstm_scan(
    const float* __restrict__ xw,    // [T, 4H]
    const float* __restrict__ Whh,   // [4H, H]
    float* __restrict__ out)         // [T, H]
{
    __shared__ float h_s[HH];
    const int tid  = threadIdx.x;
    const int wid  = tid >> 5;
    const int lane = tid & 31;
    const int j    = blockIdx.x * 5 + wid;

    float wI[20], wF[20], wG[20], wO[20];
    {
        const float* p0 = Whh + (0 * HH + j) * HH + lane;
        const float* p1 = Whh + (1 * HH + j) * HH + lane;
        const float* p2 = Whh + (2 * HH + j) * HH + lane;
        const float* p3 = Whh + (3 * HH + j) * HH + lane;
        #pragma unroll
        for (int k = 0; k < 20; k++) {
            wI[k] = p0[32 * k]; wF[k] = p1[32 * k];
            wG[k] = p2[32 * k]; wO[k] = p3[32 * k];
        }
    }
    #pragma unroll
    for (int i = 0; i < 4; i++) h_s[tid + 160 * i] = 0.f;
    float c = 0.f;          // live in lane 0
    __syncthreads();

    for (int t = 0; t < TT; t++) {
        float xwv = 0.f;
        if (lane < 4) xwv = __ldg(&xw[t * G4 + lane * HH + j]);

        float aI = 0.f, aF = 0.f, aG = 0.f, aO = 0.f;
        #pragma unroll
        for (int k = 0; k < 20; k++) {
            float hv = h_s[lane + 32 * k];
            aI += wI[k] * hv; aF += wF[k] * hv;
            aG += wG[k] * hv; aO += wO[k] * hv;
        }
        #pragma unroll
        for (int off = 16; off; off >>= 1) {
            aI += __shfl_down_sync(0xffffffffu, aI, off);
            aF += __shfl_down_sync(0xffffffffu, aF, off);
            aG += __shfl_down_sync(0xffffffffu, aG, off);
            aO += __shfl_down_sync(0xffffffffu, aO, off);
        }
        float xI = __shfl_sync(0xffffffffu, xwv, 0);
        float xF = __shfl_sync(0xffffffffu, xwv, 1);
        float xG = __shfl_sync(0xffffffffu, xwv, 2);
        float xO = __shfl_sync(0xffffffffu, xwv, 3);

        const int nb = (t + 1) & 1;
        if (lane == 0) {
            float iv = 1.f / (1.f + expf(-(aI + xI)));
            float fv = 1.f / (1.f + expf(-(aF + xF)));
            float gv = tanhf(aG + xG);
            float ov = 1.f / (1.f + expf(-(aO + xO)));
            c = fv * c + iv * gv;
            float hv = ov * tanhf(c);
            out[t * HH + j] = hv;
            *((volatile float*)&g_hbuf[nb * HH + j]) = hv;
            __threadfence();
        }
        __syncthreads();                     // block writes done
        if (tid == 0) {
            atomicAdd(&g_ctr[t], 1);
            while (*((volatile int*)&g_ctr[t]) < SB) { }
            __threadfence();
        }
        __syncthreads();                     // all blocks published h(t+1)
        #pragma unroll
        for (int i = 0; i < 4; i++)
            h_s[tid + 160 * i] = *((volatile float*)&g_hbuf[nb * HH + tid + 160 * i]);
        __syncthreads();                     // h_s ready for next step
    }
}

// ---------------- GCN helpers ----------------
__global__ void k_deg_count(const int* __restrict__ ei) {
    int e = blockIdx.x * blockDim.x + threadIdx.x;
    if (e < NE) atomicAdd(&g_deg[ei[NE + e]], 1.f);   // exact integer counts
}
__global__ void k_deg_fin() {
    int i = blockIdx.x * blockDim.x + threadIdx.x;
    if (i < NN) g_dinv[i] = rsqrtf(g_deg[i] + 1.f);   // +1 self loop
}
__global__ void k_scatter(const int* __restrict__ ei, const float* __restrict__ h, int N) {
    int total = (NE + NN) * N;
    int st = gridDim.x * blockDim.x;
    for (int idx = blockIdx.x * blockDim.x + threadIdx.x; idx < total; idx += st) {
        int e = idx / N, cidx = idx - e * N;
        int s, d;
        if (e < NE) { s = ei[e]; d = ei[NE + e]; }
        else        { s = e - NE; d = s; }
        atomicAdd(&g_agg[d * N + cidx], g_dinv[s] * g_dinv[d] * h[s * N + cidx]);
    }
}
__global__ void k_act_stats(const float* __restrict__ b, int N) {
    int total = NN * N;
    int st = gridDim.x * blockDim.x;
    for (int idx = blockIdx.x * blockDim.x + threadIdx.x; idx < total; idx += st) {
        int cidx = idx % N;
        float v = g_agg[idx] + b[cidx];
        v = (v > 0.f) ? v : 0.01f * v;     // leaky_relu slope 0.01
        g_agg[idx] = v;
        atomicAdd(&g_cs1[cidx], v);
        atomicAdd(&g_cs2[cidx], v * v);
    }
}
__global__ void k_bn(float* __restrict__ xout, int N) {
    const float inv = 1.f / (float)NN;
    int total = NN * N;
    int st = gridDim.x * blockDim.x;
    for (int idx = blockIdx.x * blockDim.x + threadIdx.x; idx < total; idx += st) {
        int cidx = idx % N;
        float m  = g_cs1[cidx] * inv;
        float vr = g_cs2[cidx] * inv - m * m;       // biased variance
        xout[idx] = (g_agg[idx] - m) * rsqrtf(vr + 1e-5f);
    }
}

// ---------------- segment-sum pool + FC head (single block) ----------------
__global__ void __launch_bounds__(256) k_pool_fc(
    const float* __restrict__ x,            // [1024, 50]
    const float* __restrict__ gender, const float* __restrict__ handed,
    const float* __restrict__ W1, const float* __restrict__ b1,   // [32,52],[32]
    const float* __restrict__ W2, const float* __restrict__ b2,   // [16,32],[16]
    const float* __restrict__ W3, const float* __restrict__ b3,   // [1,16],[1]
    float* __restrict__ outp)
{
    __shared__ float xp[16][52];
    __shared__ float y1[16][32];
    __shared__ float y2[16][16];
    int tid = threadIdx.x;
    for (int idx = tid; idx < 16 * 50; idx += 256) {
        int bb = idx / 50, cc = idx % 50;
        float s = 0.f;
        for (int r = 0; r < 64; r++) s += x[(bb * 64 + r) * 50 + cc];
        xp[bb][cc] = s;
    }
    if (tid < 16) { xp[tid][50] = gender[tid]; xp[tid][51] = handed[tid]; }
    __syncthreads();
    for (int idx = tid; idx < 16 * 32; idx += 256) {
        int bb = idx >> 5, o = idx & 31;
        float s = b1[o];
        for (int k = 0; k < 52; k++) s += xp[bb][k] * W1[o * 52 + k];
        y1[bb][o] = s;
    }
    __syncthreads();
    {
        int bb = tid >> 4, o = tid & 15;   // 256 threads == 16*16
        float s = b2[o];
        for (int k = 0; k < 32; k++) s += y1[bb][k] * W2[o * 32 + k];
        y2[bb][o] = s;
    }
    __syncthreads();
    if (tid < 16) {
        float s = b3[0];
        for (int k = 0; k < 16; k++) s += y2[tid][k] * W3[k];
        outp[tid] = s;
    }
}

// ---------------- orchestration ----------------
extern "C" void kernel_launch(void* const* d_in, const int* in_sizes, int n_in,
                              void* d_out, int out_size)
{
    const float* x_in   = (const float*)d_in[0];
    const int*   ei     = (const int*)  d_in[1];
    const float* gender = (const float*)d_in[2];
    const float* handed = (const float*)d_in[3];
    const float* Wih[3] = {(const float*)d_in[4],  (const float*)d_in[8],  (const float*)d_in[12]};
    const float* Whh[3] = {(const float*)d_in[5],  (const float*)d_in[9],  (const float*)d_in[13]};
    const float* bih[3] = {(const float*)d_in[6],  (const float*)d_in[10], (const float*)d_in[14]};
    const float* bhh[3] = {(const float*)d_in[7],  (const float*)d_in[11], (const float*)d_in[15]};
    const float* gW[4]  = {(const float*)d_in[16], (const float*)d_in[18], (const float*)d_in[20], (const float*)d_in[22]};
    const float* gB[4]  = {(const float*)d_in[17], (const float*)d_in[19], (const float*)d_in[21], (const float*)d_in[23]};

    float *xw, *seqA, *seqB, *gh, *agg, *deg, *dinv, *cs1, *cs2;
    cudaGetSymbolAddress((void**)&xw,   g_xw);
    cudaGetSymbolAddress((void**)&seqA, g_seqA);
    cudaGetSymbolAddress((void**)&seqB, g_seqB);
    cudaGetSymbolAddress((void**)&gh,   g_gh);
    cudaGetSymbolAddress((void**)&agg,  g_agg);
    cudaGetSymbolAddress((void**)&deg,  g_deg);
    cudaGetSymbolAddress((void**)&cs1,  g_cs1);
    cudaGetSymbolAddress((void**)&cs2,  g_cs2);
    (void)dinv; (void)in_sizes; (void)n_in; (void)out_size;

    dim3 gemmGrid(G4 / 64, TT / 128);   // (40, 8)

    // ---- LSTM layer 0 ----
    k_gemm_nt<<<gemmGrid, 256>>>(x_in, Wih[0], bih[0], bhh[0], xw, TT, G4, LEN0);
    k_zero_ctr<<<4, 256>>>();
    k_lstm_scan<<<SB, 160>>>(xw, Whh[0], seqA);
    // ---- LSTM layer 1 ----
    k_gemm_nt<<<gemmGrid, 256>>>(seqA, Wih[1], bih[1], bhh[1], xw, TT, G4, HH);
    k_zero_ctr<<<4, 256>>>();
    k_lstm_scan<<<SB, 160>>>(xw, Whh[1], seqB);
    // ---- LSTM layer 2 ----
    k_gemm_nt<<<gemmGrid, 256>>>(seqB, Wih[2], bih[2], bhh[2], xw, TT, G4, HH);
    k_zero_ctr<<<4, 256>>>();
    k_lstm_scan<<<SB, 160>>>(xw, Whh[2], seqA);

    // ---- degrees / symmetric norm ----
    k_zero_f<<<4, 256>>>(deg, NN);
    k_deg_count<<<64, 256>>>(ei);
    k_deg_fin<<<4, 256>>>();

    // ---- 4 GCN layers ----
    int dims[5] = {HH, 320, 180, 90, 50};
    const float* xcur = seqA;
    float* bufs[2] = {seqB, seqA};
    for (int l = 0; l < 4; l++) {
        int In = dims[l], Out = dims[l + 1];
        k_gemm_nn<<<dim3((Out + 63) / 64, NN / 64), 256>>>(xcur, gW[l], gh, Out, In);
        k_zero_f<<<320, 256>>>(agg, NN * Out);
        k_scatter<<<1024, 256>>>(ei, gh, Out);
        k_zero_f<<<2, 256>>>(cs1, Out);
        k_zero_f<<<2, 256>>>(cs2, Out);
        k_act_stats<<<512, 256>>>(gB[l], Out);
        k_bn<<<512, 256>>>(bufs[l & 1], Out);
        xcur = bufs[l & 1];
    }

    // ---- pool + FC head ----
    k_pool_fc<<<1, 256>>>(xcur, gender, handed,
                          (const float*)d_in[24], (const float*)d_in[25],
                          (const float*)d_in[26], (const float*)d_in[27],
                          (const float*)d_in[28], (const float*)d_in[29],
                          (float*)d_out);
}